// round 11
// baseline (speedup 1.0000x reference)
#include <cuda_runtime.h>
#include <cuda_bf16.h>

// One-hot: x [8,1024] int32 -> out [8,1024,32000] fp32 (1.048 GB of stores).
// FINAL: best-measured variant (R7). Fused eighth-row blocks: grid = 65536
// (8 per row), 256 threads, 1000 float4 per block = 3 full iters + 232-thread
// tail. Fine-grained blocks self-balance through the HW work queue (the
// single-wave persistent variant regressed 25% from per-CTA spread); evict-
// first __stcs streaming stores; the 1.0f overwrite is done by the same
// thread that zeroed that slot (tid == o & 255), so same-thread same-address
// store ordering guarantees the final value with no fence and no 2nd kernel.
//
// Measured roofline evidence: SM-store fill, driver memset node, and
// STG.256 all converge at ~7.2 TB/s (~91% of 8 TB/s spec) — the sustained
// pure-write ceiling on this chip. Kernel 136.4 us vs 131 us spec floor.

static constexpr int NUM_CLASS = 32000;
static constexpr int NC4       = NUM_CLASS / 4;    // 8000 float4 per row
static constexpr int ROWS      = 8 * 1024;         // 8192
static constexpr int CHUNK     = NC4 / 8;          // 1000 float4 per block
static constexpr int THREADS   = 256;
static constexpr int FULL_IT   = CHUNK / THREADS;  // 3
static constexpr int TAIL      = CHUNK - FULL_IT * THREADS;  // 232

__global__ void __launch_bounds__(THREADS)
onehot_eighth_kernel(const int* __restrict__ x, float4* __restrict__ out)
{
    const int row = blockIdx.x >> 3;
    const int c   = blockIdx.x & 7;
    const int tid = threadIdx.x;

    const int t = __ldg(x + row);                  // broadcast; stores don't wait

    float4* p = out + (long long)row * NC4 + c * CHUNK;
    const float4 z = make_float4(0.f, 0.f, 0.f, 0.f);

#pragma unroll
    for (int i = 0; i < FULL_IT; ++i) {
        __stcs(p + i * THREADS + tid, z);          // evict-first streaming store
    }
    if (tid < TAIL) {
        __stcs(p + FULL_IT * THREADS + tid, z);
    }

    // hot-slot overwrite: offset of the hot float4 within this chunk
    const int o = (t >> 2) - c * CHUNK;
    if (o >= 0 && o < CHUNK && (o & (THREADS - 1)) == tid) {
        reinterpret_cast<float*>(p + o)[t & 3] = 1.0f;  // same thread zeroed p[o]
    }
}

extern "C" void kernel_launch(void* const* d_in, const int* in_sizes, int n_in,
                              void* d_out, int out_size)
{
    const int* x = (const int*)d_in[0];
    onehot_eighth_kernel<<<ROWS * 8, THREADS>>>(x, (float4*)d_out);
}